// round 5
// baseline (speedup 1.0000x reference)
#include <cuda_runtime.h>
#include <cuda_fp16.h>
#include <cstdint>

#define DINLINE __device__ __forceinline__

// ---------------- helpers ----------------

DINLINE uint32_t smem_u32(const void* p) {
    uint32_t a;
    asm("{ .reg .u64 t; cvta.to.shared.u64 t, %1; cvt.u32.u64 %0, t; }"
        : "=r"(a) : "l"(p));
    return a;
}

DINLINE void ldsm_x4(uint32_t& r0, uint32_t& r1, uint32_t& r2, uint32_t& r3,
                     uint32_t addr) {
    asm volatile("ldmatrix.sync.aligned.m8n8.x4.shared.b16 {%0,%1,%2,%3}, [%4];"
                 : "=r"(r0), "=r"(r1), "=r"(r2), "=r"(r3) : "r"(addr));
}

DINLINE void ldsm_x4_trans(uint32_t& r0, uint32_t& r1, uint32_t& r2, uint32_t& r3,
                           uint32_t addr) {
    asm volatile("ldmatrix.sync.aligned.m8n8.x4.trans.shared.b16 {%0,%1,%2,%3}, [%4];"
                 : "=r"(r0), "=r"(r1), "=r"(r2), "=r"(r3) : "r"(addr));
}

DINLINE void mma16816(float* c, const uint32_t* a, uint32_t b0, uint32_t b1) {
    asm volatile(
        "mma.sync.aligned.m16n8k16.row.col.f32.f16.f16.f32 "
        "{%0,%1,%2,%3}, {%4,%5,%6,%7}, {%8,%9}, {%0,%1,%2,%3};"
        : "+f"(c[0]), "+f"(c[1]), "+f"(c[2]), "+f"(c[3])
        : "r"(a[0]), "r"(a[1]), "r"(a[2]), "r"(a[3]), "r"(b0), "r"(b1));
}

DINLINE float fsigmoid(float x) {
    // sigmoid(x/8) = 1 / (1 + 2^(-x*log2(e)/8)); ex2/rcp approx err ~1e-6
    const float C = 0.18033688011112042f;  // log2(e)/8
    float e, r;
    asm("ex2.approx.f32 %0, %1;" : "=f"(e) : "f"(-x * C));
    asm("rcp.approx.f32 %0, %1;" : "=f"(r) : "f"(1.0f + e));
    return r;
}

DINLINE uint32_t packh2(float a, float b) {
    __half2 h = __floats2half2_rn(a, b);
    return *reinterpret_cast<uint32_t*>(&h);
}

// ---------------- problem constants ----------------
// B=4, H=16, S=2048, D=64.  64 heads x 8 q-tiles of 256 rows = 512 CTAs.
static constexpr int S_LEN  = 2048;
static constexpr int D_DIM  = 64;
static constexpr int QTILE  = 256;
static constexpr int KTILE  = 64;
static constexpr int NKT    = S_LEN / KTILE;   // 32
static constexpr int NWARP  = 16;
static constexpr int NTHR   = NWARP * 32;      // 512

// SMEM (halves, row stride 72 => 144B rows, conflict-free for ldmatrix)
static constexpr int STRIDE   = 72;
static constexpr int SM_K_OFF = 0;                       // bytes
static constexpr int SM_V_OFF = KTILE * STRIDE * 2;      // 9216
static constexpr int SMEM_BYTES = QTILE * STRIDE * 2;    // 36864 (Q stage reuses K/V area)

__global__ void __launch_bounds__(NTHR, 1) sigattn_kernel(
    const float* __restrict__ gq, const float* __restrict__ gk,
    const float* __restrict__ gv, float* __restrict__ gout)
{
    extern __shared__ char smem[];
    const uint32_t sb = smem_u32(smem);
    const int tid  = threadIdx.x;
    const int wid  = tid >> 5;
    const int lane = tid & 31;

    const int bx = blockIdx.x;
    const int qt = bx & 7;           // q-tile within head
    const int bh = bx >> 3;          // flattened (b,h)
    const size_t head_base = (size_t)bh * S_LEN * D_DIM;
    const float* qb = gq + head_base + (size_t)qt * QTILE * D_DIM;
    const float* kb = gk + head_base;
    const float* vb = gv + head_base;
    float*       ob = gout + head_base + (size_t)qt * QTILE * D_DIM;

    // ---- stage Q (fp32 -> f16) into SMEM, then ldmatrix into registers ----
    {
        int row = tid >> 1;                 // 0..255
        int c0  = (tid & 1) * 32;           // 0 or 32
        const float4* src = reinterpret_cast<const float4*>(qb + (size_t)row * D_DIM + c0);
        uint32_t* dst = reinterpret_cast<uint32_t*>(smem) + (row * STRIDE + c0) / 2;
        #pragma unroll
        for (int i = 0; i < 8; i++) {
            float4 f = src[i];
            dst[2 * i]     = packh2(f.x, f.y);
            dst[2 * i + 1] = packh2(f.z, f.w);
        }
    }
    __syncthreads();

    // Q fragments: qf[kstep][4] regs, warp rows 16*wid .. +15
    uint32_t qf[4][4];
    {
        const int idx = lane & 15;
        const int seg = lane >> 4;          // 0/1
        #pragma unroll
        for (int s = 0; s < 4; s++) {
            uint32_t addr = sb + (uint32_t)(((16 * wid + idx) * STRIDE) + 16 * s + 8 * seg) * 2;
            ldsm_x4(qf[s][0], qf[s][1], qf[s][2], qf[s][3], addr);
        }
    }
    __syncthreads();   // Q fully in registers before K/V overwrite SMEM

    // ---- O accumulators: 8 d-tiles x 4 fp32 ----
    float oc[8][4];
    #pragma unroll
    for (int j = 0; j < 8; j++)
        #pragma unroll
        for (int r = 0; r < 4; r++) oc[j][r] = 0.0f;

    const int idx = lane & 15;
    const int seg = lane >> 4;

    for (int kt = 0; kt < NKT; kt++) {
        // ---- load K,V 64x64 tiles (fp32 -> f16) ----
        {
            int row = tid >> 3;             // 0..63
            int c0  = (tid & 7) * 8;        // 0..56
            size_t gofs = ((size_t)kt * KTILE + row) * D_DIM + c0;
            const float4* ksrc = reinterpret_cast<const float4*>(kb + gofs);
            const float4* vsrc = reinterpret_cast<const float4*>(vb + gofs);
            float4 k0 = ksrc[0], k1 = ksrc[1];
            float4 v0 = vsrc[0], v1 = vsrc[1];
            uint32_t* kd = reinterpret_cast<uint32_t*>(smem + SM_K_OFF) + (row * STRIDE + c0) / 2;
            uint32_t* vd = reinterpret_cast<uint32_t*>(smem + SM_V_OFF) + (row * STRIDE + c0) / 2;
            kd[0] = packh2(k0.x, k0.y); kd[1] = packh2(k0.z, k0.w);
            kd[2] = packh2(k1.x, k1.y); kd[3] = packh2(k1.z, k1.w);
            vd[0] = packh2(v0.x, v0.y); vd[1] = packh2(v0.z, v0.w);
            vd[2] = packh2(v1.x, v1.y); vd[3] = packh2(v1.z, v1.w);
        }
        __syncthreads();

        // ---- QK: S[16 x 64] = Q @ K^T ----
        float sc[8][4];
        #pragma unroll
        for (int j = 0; j < 8; j++)
            #pragma unroll
            for (int r = 0; r < 4; r++) sc[j][r] = 0.0f;

        #pragma unroll
        for (int s = 0; s < 4; s++) {
            #pragma unroll
            for (int j = 0; j < 4; j++) {   // key pair-of-n8 tiles
                uint32_t r0, r1, r2, r3;
                uint32_t addr = sb + SM_K_OFF +
                    (uint32_t)(((16 * j + idx) * STRIDE) + 16 * s + 8 * seg) * 2;
                ldsm_x4(r0, r1, r2, r3, addr);
                mma16816(sc[2 * j],     qf[s], r0, r2);
                mma16816(sc[2 * j + 1], qf[s], r1, r3);
            }
        }

        // ---- sigmoid + repack C-frags -> A-frags (P) ----
        uint32_t pf[4][4];
        #pragma unroll
        for (int t = 0; t < 4; t++) {
            pf[t][0] = packh2(fsigmoid(sc[2 * t][0]),     fsigmoid(sc[2 * t][1]));
            pf[t][1] = packh2(fsigmoid(sc[2 * t][2]),     fsigmoid(sc[2 * t][3]));
            pf[t][2] = packh2(fsigmoid(sc[2 * t + 1][0]), fsigmoid(sc[2 * t + 1][1]));
            pf[t][3] = packh2(fsigmoid(sc[2 * t + 1][2]), fsigmoid(sc[2 * t + 1][3]));
        }

        // ---- PV: O += P @ V ----
        #pragma unroll
        for (int t = 0; t < 4; t++) {       // key k-steps of 16
            #pragma unroll
            for (int m = 0; m < 4; m++) {   // d pair-of-n8 tiles
                uint32_t r0, r1, r2, r3;
                uint32_t addr = sb + SM_V_OFF +
                    (uint32_t)(((16 * t + idx) * STRIDE) + 16 * m + 8 * seg) * 2;
                ldsm_x4_trans(r0, r1, r2, r3, addr);
                mma16816(oc[2 * m],     pf[t], r0, r1);
                mma16816(oc[2 * m + 1], pf[t], r2, r3);
            }
        }
        __syncthreads();   // compute done before next iter overwrites K/V
    }

    // ---- epilogue: write O (fp32) ----
    {
        const int g  = lane >> 2;
        const int tg = lane & 3;
        const int r0 = 16 * wid + g;
        const int r1 = r0 + 8;
        #pragma unroll
        for (int j = 0; j < 8; j++) {
            int c = 8 * j + 2 * tg;
            *reinterpret_cast<float2*>(ob + (size_t)r0 * D_DIM + c) =
                make_float2(oc[j][0], oc[j][1]);
            *reinterpret_cast<float2*>(ob + (size_t)r1 * D_DIM + c) =
                make_float2(oc[j][2], oc[j][3]);
        }
    }
}

extern "C" void kernel_launch(void* const* d_in, const int* in_sizes, int n_in,
                              void* d_out, int out_size) {
    (void)in_sizes; (void)n_in; (void)out_size;
    const float* q = (const float*)d_in[0];
    const float* k = (const float*)d_in[1];
    const float* v = (const float*)d_in[2];
    float* out = (float*)d_out;

    cudaFuncSetAttribute(sigattn_kernel,
                         cudaFuncAttributeMaxDynamicSharedMemorySize, SMEM_BYTES);
    sigattn_kernel<<<512, NTHR, SMEM_BYTES>>>(q, k, v, out);
}

// round 6
// speedup vs baseline: 1.5080x; 1.5080x over previous
#include <cuda_runtime.h>
#include <cuda_fp16.h>
#include <cstdint>

#define DINLINE __device__ __forceinline__

// ---------------- helpers ----------------

DINLINE uint32_t smem_u32(const void* p) {
    uint32_t a;
    asm("{ .reg .u64 t; cvta.to.shared.u64 t, %1; cvt.u32.u64 %0, t; }"
        : "=r"(a) : "l"(p));
    return a;
}

DINLINE void ldsm_x4(uint32_t& r0, uint32_t& r1, uint32_t& r2, uint32_t& r3,
                     uint32_t addr) {
    asm volatile("ldmatrix.sync.aligned.m8n8.x4.shared.b16 {%0,%1,%2,%3}, [%4];"
                 : "=r"(r0), "=r"(r1), "=r"(r2), "=r"(r3) : "r"(addr));
}

DINLINE void ldsm_x4_trans(uint32_t& r0, uint32_t& r1, uint32_t& r2, uint32_t& r3,
                           uint32_t addr) {
    asm volatile("ldmatrix.sync.aligned.m8n8.x4.trans.shared.b16 {%0,%1,%2,%3}, [%4];"
                 : "=r"(r0), "=r"(r1), "=r"(r2), "=r"(r3) : "r"(addr));
}

DINLINE void mma16816(float* c, const uint32_t* a, uint32_t b0, uint32_t b1) {
    asm volatile(
        "mma.sync.aligned.m16n8k16.row.col.f32.f16.f16.f32 "
        "{%0,%1,%2,%3}, {%4,%5,%6,%7}, {%8,%9}, {%0,%1,%2,%3};"
        : "+f"(c[0]), "+f"(c[1]), "+f"(c[2]), "+f"(c[3])
        : "r"(a[0]), "r"(a[1]), "r"(a[2]), "r"(a[3]), "r"(b0), "r"(b1));
}

DINLINE float fsigmoid(float x) {
    // sigmoid(x/8) = 0.5 + 0.5 * tanh(x/16); single MUFU (tanh.approx, sm_75+)
    float t;
    asm("tanh.approx.f32 %0, %1;" : "=f"(t) : "f"(x * 0.0625f));
    return fmaf(0.5f, t, 0.5f);
}

DINLINE uint32_t packh2(float a, float b) {
    __half2 h = __floats2half2_rn(a, b);
    return *reinterpret_cast<uint32_t*>(&h);
}

// ---------------- problem constants ----------------
// B=4, H=16, S=2048, D=64.  64 heads x 8 q-tiles of 256 rows = 512 CTAs.
static constexpr int S_LEN  = 2048;
static constexpr int D_DIM  = 64;
static constexpr int QTILE  = 256;
static constexpr int KTILE  = 64;
static constexpr int NKT    = S_LEN / KTILE;   // 32
static constexpr int NWARP  = 16;
static constexpr int NTHR   = NWARP * 32;      // 512

// SMEM (halves, row stride 72 => 144B rows, conflict-free for ldmatrix)
static constexpr int STRIDE   = 72;
static constexpr int TILE_B   = KTILE * STRIDE * 2;      // 9216 bytes (one 64x64 f16 tile)
static constexpr int BUF_B    = 2 * TILE_B;              // K + V per stage: 18432
static constexpr int SMEM_BYTES = 2 * BUF_B;             // 36864 (double buffer; Q staging reuses)

__global__ void __launch_bounds__(NTHR, 1) sigattn_kernel(
    const float* __restrict__ gq, const float* __restrict__ gk,
    const float* __restrict__ gv, float* __restrict__ gout)
{
    extern __shared__ char smem[];
    const uint32_t sb = smem_u32(smem);
    const int tid  = threadIdx.x;
    const int wid  = tid >> 5;
    const int lane = tid & 31;

    const int bx = blockIdx.x;
    const int qt = bx & 7;           // q-tile within head
    const int bh = bx >> 3;          // flattened (b,h)
    const size_t head_base = (size_t)bh * S_LEN * D_DIM;
    const float* qb = gq + head_base + (size_t)qt * QTILE * D_DIM;
    const float* kb = gk + head_base;
    const float* vb = gv + head_base;
    float*       ob = gout + head_base + (size_t)qt * QTILE * D_DIM;

    // ---- stage Q (fp32 -> f16) into SMEM, then ldmatrix into registers ----
    {
        int row = tid >> 1;                 // 0..255
        int c0  = (tid & 1) * 32;           // 0 or 32
        const float4* src = reinterpret_cast<const float4*>(qb + (size_t)row * D_DIM + c0);
        uint32_t* dst = reinterpret_cast<uint32_t*>(smem) + (row * STRIDE + c0) / 2;
        #pragma unroll
        for (int i = 0; i < 8; i++) {
            float4 f = src[i];
            dst[2 * i]     = packh2(f.x, f.y);
            dst[2 * i + 1] = packh2(f.z, f.w);
        }
    }
    __syncthreads();

    // Q fragments: qf[kstep][4] regs, warp rows 16*wid .. +15
    uint32_t qf[4][4];
    {
        const int idx = lane & 15;
        const int seg = lane >> 4;          // 0/1
        #pragma unroll
        for (int s = 0; s < 4; s++) {
            uint32_t addr = sb + (uint32_t)(((16 * wid + idx) * STRIDE) + 16 * s + 8 * seg) * 2;
            ldsm_x4(qf[s][0], qf[s][1], qf[s][2], qf[s][3], addr);
        }
    }
    __syncthreads();   // Q fully in registers before K/V overwrite SMEM

    // per-thread K/V gmem/smem coordinates (64x64 tile, 512 threads)
    const int kvrow = tid >> 3;             // 0..63
    const int kvc0  = (tid & 7) * 8;        // 0..56
    const int kv_soff = (kvrow * STRIDE + kvc0) / 2;   // u32 index into tile

    // ---- preload tile 0 into buffer 0 ----
    {
        size_t gofs = (size_t)kvrow * D_DIM + kvc0;
        const float4* ksrc = reinterpret_cast<const float4*>(kb + gofs);
        const float4* vsrc = reinterpret_cast<const float4*>(vb + gofs);
        float4 k0 = ksrc[0], k1 = ksrc[1];
        float4 v0 = vsrc[0], v1 = vsrc[1];
        uint32_t* kd = reinterpret_cast<uint32_t*>(smem) + kv_soff;
        uint32_t* vd = reinterpret_cast<uint32_t*>(smem + TILE_B) + kv_soff;
        kd[0] = packh2(k0.x, k0.y); kd[1] = packh2(k0.z, k0.w);
        kd[2] = packh2(k1.x, k1.y); kd[3] = packh2(k1.z, k1.w);
        vd[0] = packh2(v0.x, v0.y); vd[1] = packh2(v0.z, v0.w);
        vd[2] = packh2(v1.x, v1.y); vd[3] = packh2(v1.z, v1.w);
    }
    __syncthreads();

    // ---- O accumulators: 8 d-tiles x 4 fp32 ----
    float oc[8][4];
    #pragma unroll
    for (int j = 0; j < 8; j++)
        #pragma unroll
        for (int r = 0; r < 4; r++) oc[j][r] = 0.0f;

    const int idx = lane & 15;
    const int seg = lane >> 4;
    // loop-invariant pieces of ldmatrix addresses
    const uint32_t lds_base = sb + (uint32_t)((idx * STRIDE + 8 * seg) * 2);

    for (int kt = 0; kt < NKT; kt++) {
        const uint32_t cur_off  = (uint32_t)((kt & 1) * BUF_B);
        const uint32_t next_off = (uint32_t)(((kt + 1) & 1) * BUF_B);

        // ---- prefetch tile kt+1 (fp32 -> f16 in regs); lands during compute ----
        uint32_t kr[4], vr[4];
        {
            int ktn = (kt + 1 < NKT) ? kt + 1 : kt;   // clamp (last-iter data unused)
            size_t gofs = ((size_t)ktn * KTILE + kvrow) * D_DIM + kvc0;
            const float4* ksrc = reinterpret_cast<const float4*>(kb + gofs);
            const float4* vsrc = reinterpret_cast<const float4*>(vb + gofs);
            float4 k0 = ksrc[0], k1 = ksrc[1];
            float4 v0 = vsrc[0], v1 = vsrc[1];
            kr[0] = packh2(k0.x, k0.y); kr[1] = packh2(k0.z, k0.w);
            kr[2] = packh2(k1.x, k1.y); kr[3] = packh2(k1.z, k1.w);
            vr[0] = packh2(v0.x, v0.y); vr[1] = packh2(v0.z, v0.w);
            vr[2] = packh2(v1.x, v1.y); vr[3] = packh2(v1.z, v1.w);
        }

        // ---- QK: S[16 x 64] = Q @ K^T  (K tile at cur_off) ----
        float sc[8][4];
        #pragma unroll
        for (int j = 0; j < 8; j++)
            #pragma unroll
            for (int r = 0; r < 4; r++) sc[j][r] = 0.0f;

        #pragma unroll
        for (int s = 0; s < 4; s++) {
            #pragma unroll
            for (int j = 0; j < 4; j++) {   // key pair-of-n8 tiles
                uint32_t r0, r1, r2, r3;
                uint32_t addr = lds_base + cur_off +
                    (uint32_t)((16 * j * STRIDE + 16 * s) * 2);
                ldsm_x4(r0, r1, r2, r3, addr);
                mma16816(sc[2 * j],     qf[s], r0, r2);
                mma16816(sc[2 * j + 1], qf[s], r1, r3);
            }
        }

        // ---- sigmoid + repack C-frags -> A-frags (P) ----
        uint32_t pf[4][4];
        #pragma unroll
        for (int t = 0; t < 4; t++) {
            pf[t][0] = packh2(fsigmoid(sc[2 * t][0]),     fsigmoid(sc[2 * t][1]));
            pf[t][1] = packh2(fsigmoid(sc[2 * t][2]),     fsigmoid(sc[2 * t][3]));
            pf[t][2] = packh2(fsigmoid(sc[2 * t + 1][0]), fsigmoid(sc[2 * t + 1][1]));
            pf[t][3] = packh2(fsigmoid(sc[2 * t + 1][2]), fsigmoid(sc[2 * t + 1][3]));
        }

        // ---- PV: O += P @ V  (V tile at cur_off + TILE_B) ----
        #pragma unroll
        for (int t = 0; t < 4; t++) {       // key k-steps of 16
            #pragma unroll
            for (int m = 0; m < 4; m++) {   // d pair-of-n8 tiles
                uint32_t r0, r1, r2, r3;
                uint32_t addr = lds_base + cur_off + (uint32_t)TILE_B +
                    (uint32_t)((16 * t * STRIDE + 16 * m) * 2);
                ldsm_x4_trans(r0, r1, r2, r3, addr);
                mma16816(oc[2 * m],     pf[t], r0, r1);
                mma16816(oc[2 * m + 1], pf[t], r2, r3);
            }
        }

        __syncthreads();   // all warps done reading next buffer's previous contents

        // ---- store prefetched tile kt+1 into the other buffer ----
        if (kt + 1 < NKT) {
            uint32_t* kd = reinterpret_cast<uint32_t*>(smem + next_off) + kv_soff;
            uint32_t* vd = reinterpret_cast<uint32_t*>(smem + next_off + TILE_B) + kv_soff;
            kd[0] = kr[0]; kd[1] = kr[1]; kd[2] = kr[2]; kd[3] = kr[3];
            vd[0] = vr[0]; vd[1] = vr[1]; vd[2] = vr[2]; vd[3] = vr[3];
        }
        __syncthreads();
    }

    // ---- epilogue: write O (fp32) ----
    {
        const int g  = lane >> 2;
        const int tg = lane & 3;
        const int r0 = 16 * wid + g;
        const int r1 = r0 + 8;
        #pragma unroll
        for (int j = 0; j < 8; j++) {
            int c = 8 * j + 2 * tg;
            *reinterpret_cast<float2*>(ob + (size_t)r0 * D_DIM + c) =
                make_float2(oc[j][0], oc[j][1]);
            *reinterpret_cast<float2*>(ob + (size_t)r1 * D_DIM + c) =
                make_float2(oc[j][2], oc[j][3]);
        }
    }
}

extern "C" void kernel_launch(void* const* d_in, const int* in_sizes, int n_in,
                              void* d_out, int out_size) {
    (void)in_sizes; (void)n_in; (void)out_size;
    const float* q = (const float*)d_in[0];
    const float* k = (const float*)d_in[1];
    const float* v = (const float*)d_in[2];
    float* out = (float*)d_out;

    cudaFuncSetAttribute(sigattn_kernel,
                         cudaFuncAttributeMaxDynamicSharedMemorySize, SMEM_BYTES);
    sigattn_kernel<<<512, NTHR, SMEM_BYTES>>>(q, k, v, out);
}